// round 17
// baseline (speedup 1.0000x reference)
#include <cuda_runtime.h>
#include <cuda_bf16.h>
#include <cstdint>

#define C       256
#define N       4096
#define HEADS   4
#define HD      64
#define GROUPS  32
#define GSIZE   (C / GROUPS)
#define GELEMS  (GSIZE * N)
#define GN_EPS  1e-6f
// 0.125 * log2(e): softmax uses ex2 directly
#define QSCALE2 0.18033688011112042f
#define NSPLIT  4

// bf16 scratch. Channel (or key) index pair-permuted within 16-blocks
// ([0,1,8,9,2,3,10,11,4,5,12,13,6,7,14,15]) so MMA fragments are LDS.64.
__device__ __nv_bfloat16 g_hnb[N * C];     // groupnormed input [p][perm c]
__device__ __nv_bfloat16 g_wb [3 * C * C]; // weights bf16 [o][perm c]
__device__ __nv_bfloat16 g_qb [N * C];
__device__ __nv_bfloat16 g_kb [N * C];
__device__ __nv_bfloat16 g_vtb[C * N];     // V transposed [c][perm p]
__device__ float g_po[NSPLIT * N * C];     // unnormalized O partials
__device__ float g_pl[NSPLIT * HEADS * N]; // l partials [split][head][p]
__device__ float g_ot [N * C];             // proj B operand [p2][perm8 c], tf32
__device__ float g_wpt[C * C];             // Wp tf32 [o][perm8 c]
__device__ float g_gs [GROUPS * 8];        // GN partial sums [group][slice]
__device__ float g_gs2[GROUPS * 8];        // GN partial sumsq

__device__ __forceinline__ int perm16(int i) {
    int b = i & ~15, l = i & 15, j = l >> 1, o = l & 1;
    int p = (j < 4) ? 4 * j : 4 * (j - 4) + 2;
    return b + p + o;
}
__device__ __forceinline__ int wpos8(int j) {
    return (j < 4) ? 2 * j : 2 * (j - 4) + 1;
}
__device__ __forceinline__ uint32_t pk_bf2(float lo, float hi) {
    uint32_t d;
    asm("cvt.rn.bf16x2.f32 %0, %1, %2;" : "=r"(d) : "f"(hi), "f"(lo));
    return d;
}
__device__ __forceinline__ float ex2(float x) {
    float r;
    asm("ex2.approx.f32 %0, %1;" : "=f"(r) : "f"(x));
    return r;
}
__device__ __forceinline__ float tf32r(float f) {
    uint32_t u;
    asm("cvt.rna.tf32.f32 %0, %1;" : "=r"(u) : "f"(f));
    return __uint_as_float(u);
}
__device__ __forceinline__ void mma_bf16(float c[4],
        uint32_t a0, uint32_t a1, uint32_t a2, uint32_t a3,
        uint32_t b0, uint32_t b1) {
    asm volatile("mma.sync.aligned.m16n8k16.row.col.f32.bf16.bf16.f32 "
                 "{%0,%1,%2,%3}, {%4,%5,%6,%7}, {%8,%9}, {%0,%1,%2,%3};"
                 : "+f"(c[0]), "+f"(c[1]), "+f"(c[2]), "+f"(c[3])
                 : "r"(a0), "r"(a1), "r"(a2), "r"(a3), "r"(b0), "r"(b1));
}
__device__ __forceinline__ void mma_tf32(float c[4],
        uint32_t a0, uint32_t a1, uint32_t a2, uint32_t a3,
        uint32_t b0, uint32_t b1) {
    asm volatile("mma.sync.aligned.m16n8k8.row.col.f32.tf32.tf32.f32 "
                 "{%0,%1,%2,%3}, {%4,%5,%6,%7}, {%8,%9}, {%0,%1,%2,%3};"
                 : "+f"(c[0]), "+f"(c[1]), "+f"(c[2]), "+f"(c[3])
                 : "r"(a0), "r"(a1), "r"(a2), "r"(a3), "r"(b0), "r"(b1));
}
__device__ __forceinline__ uint32_t smem_u32(const void* p) {
    uint32_t a;
    asm("{ .reg .u64 t; cvta.to.shared.u64 t, %1; cvt.u32.u64 %0, t; }"
        : "=r"(a) : "l"(p));
    return a;
}
__device__ __forceinline__ void cp16(uint32_t d, const void* s) {
    asm volatile("cp.async.cg.shared.global [%0], [%1], 16;" :: "r"(d), "l"(s));
}
#define CP_COMMIT() asm volatile("cp.async.commit_group;" ::: "memory")
#define CP_WAIT0()  asm volatile("cp.async.wait_group 0;" ::: "memory")

// ---------------------------------------------------------------------------
// Kernel 1: merged preamble. Blocks 0..255: GN partial stats.
// Blocks 256..767: weight convert (Wq/Wk/Wv bf16, Wp tf32).
// ---------------------------------------------------------------------------
__global__ void prep_kernel(const float* __restrict__ x,
                            const float* __restrict__ Wq,
                            const float* __restrict__ Wk,
                            const float* __restrict__ Wv,
                            const float* __restrict__ Wp) {
    const int bid = blockIdx.x, tid = threadIdx.x;
    if (bid < 256) {
        const int g = bid >> 3, sl = bid & 7;
        float s = 0.f, s2 = 0.f;
#pragma unroll
        for (int i = 0; i < 4; i++) {
            int e = i * 256 + tid;
            int c = e >> 7, q = e & 127;
            float4 v = *(const float4*)(x + (g * 8 + c) * N + sl * 512 + q * 4);
            s  += (v.x + v.y) + (v.z + v.w);
            s2 += (v.x * v.x + v.y * v.y) + (v.z * v.z + v.w * v.w);
        }
        __shared__ float r1[256], r2[256];
        r1[tid] = s; r2[tid] = s2;
        __syncthreads();
        for (int st = 128; st > 0; st >>= 1) {
            if (tid < st) { r1[tid] += r1[tid + st]; r2[tid] += r2[tid + st]; }
            __syncthreads();
        }
        if (tid == 0) {
            g_gs [g * 8 + sl] = r1[0];
            g_gs2[g * 8 + sl] = r2[0];
        }
    } else {
        const int wb = bid - 256;
        const int z = wb >> 7;
        int e = (wb & 127) * 256 + tid;          // 0..32767 float2
        int o = e >> 7, c2 = e & 127;
        if (z < 3) {
            const float* W = (z == 0) ? Wq : (z == 1) ? Wk : Wv;
            uint32_t* wbw = (uint32_t*)g_wb + z * 32768;
            float2 wv = *(const float2*)(W + o * 256 + 2 * c2);
            wbw[o * 128 + (c2 >> 3) * 8 + wpos8(c2 & 7)] = pk_bf2(wv.x, wv.y);
        } else {
            float2 wv = *(const float2*)(Wp + o * 256 + 2 * c2);
            int cbase = (2 * c2) & ~7, cl = (2 * c2) & 7;
            g_wpt[o * 256 + cbase + wpos8(cl)]     = tf32r(wv.x);
            g_wpt[o * 256 + cbase + wpos8(cl + 1)] = tf32r(wv.y);
        }
    }
}

// ---------------------------------------------------------------------------
// Kernel 1b: GN apply -> g_hnb bf16 [p][perm16 c] (validated r15/r16).
// ---------------------------------------------------------------------------
__global__ void gn_apply_kernel(const float* __restrict__ x,
                                const float* __restrict__ gamma,
                                const float* __restrict__ beta) {
    const int chunk = blockIdx.x, b = blockIdx.y, tid = threadIdx.x;
    __shared__ float T[16 * 516];
    __shared__ float sc[16], sh[16], murs[4];

    if (tid < 2) {
        float s = 0.f, s2 = 0.f;
#pragma unroll
        for (int i = 0; i < 8; i++) {
            s  += g_gs [(2 * b + tid) * 8 + i];
            s2 += g_gs2[(2 * b + tid) * 8 + i];
        }
        float mu = s * (1.f / GELEMS);
        float var = s2 * (1.f / GELEMS) - mu * mu;
        murs[tid] = mu; murs[2 + tid] = rsqrtf(var + GN_EPS);
    }
    __syncthreads();
    if (tid < 16) {
        int grp = tid >> 3;
        float s = murs[2 + grp] * gamma[16 * b + tid];
        sc[tid] = s;
        sh[tid] = beta[16 * b + tid] - murs[grp] * s;
    }

    const int pc = chunk * 512;
    for (int e = tid; e < 2048; e += 256) {
        int r = e >> 7, c4 = e & 127;
        *(float4*)(T + r * 516 + c4 * 4) =
            *(const float4*)(x + (16 * b + r) * N + pc + c4 * 4);
    }
    __syncthreads();

    uint32_t* hnw = (uint32_t*)g_hnb;
#pragma unroll
    for (int pp = 0; pp < 2; pp++) {
        const int pl = tid + pp * 256;
        float v[16];
#pragma unroll
        for (int c = 0; c < 16; c++)
            v[c] = fmaf(T[c * 516 + pl], sc[c], sh[c]);
        uint32_t wd[8];
#pragma unroll
        for (int j = 0; j < 8; j++)
            wd[wpos8(j)] = pk_bf2(v[2 * j], v[2 * j + 1]);
        uint4* dst = (uint4*)(hnw + (pc + pl) * 128 + b * 8);
        dst[0] = make_uint4(wd[0], wd[1], wd[2], wd[3]);
        dst[1] = make_uint4(wd[4], wd[5], wd[6], wd[7]);
    }
}

// ---------------------------------------------------------------------------
// Kernel 2: Q/K/V projection, bf16 mma, cp.async, CTA = 64p x 128o,
// 3 CTAs/SM, one wave (validated r16).
// ---------------------------------------------------------------------------
#define QKV_A_W   (64 * 40)
#define QKV_STG_W (QKV_A_W + 128 * 40)
#define QKV_SMEM  (2 * QKV_STG_W * 4)

__global__ __launch_bounds__(128, 3) void qkv_mma_kernel(
        const float* __restrict__ bq, const float* __restrict__ bk,
        const float* __restrict__ bv) {
    extern __shared__ uint32_t sbuf[];

    const int tid = threadIdx.x;
    const int w = tid >> 5, lane = tid & 31;
    const int g = lane >> 2, tig = lane & 3;
    const int p0 = blockIdx.x * 64;
    const int o0 = blockIdx.y * 128;
    const int z  = blockIdx.z;
    const float* bias = (z == 0) ? bq : (z == 1) ? bk : bv;

    const uint32_t* hnw = (const uint32_t*)g_hnb;
    const uint32_t* wbw = (const uint32_t*)g_wb + z * 32768;

    const uint32_t sb = smem_u32(sbuf);
    int ra[4], qa4[4], rb[8], qb4[8];
#pragma unroll
    for (int i = 0; i < 4; i++) {
        int e = i * 128 + tid;
        ra[i] = e >> 3; qa4[i] = e & 7;
    }
#pragma unroll
    for (int i = 0; i < 8; i++) {
        int e = i * 128 + tid;
        rb[i] = e >> 3; qb4[i] = e & 7;
    }

    float acc[16][4] = {};

#pragma unroll
    for (int i = 0; i < 4; i++)
        cp16(sb + (ra[i] * 40 + qa4[i] * 4) * 4,
             hnw + (p0 + ra[i]) * 128 + qa4[i] * 4);
#pragma unroll
    for (int i = 0; i < 8; i++)
        cp16(sb + (QKV_A_W + rb[i] * 40 + qb4[i] * 4) * 4,
             wbw + (o0 + rb[i]) * 128 + qb4[i] * 4);
    CP_COMMIT();

    for (int ch = 0; ch < 4; ch++) {
        CP_WAIT0();
        __syncthreads();
        if (ch < 3) {
            const uint32_t db = sb + ((ch + 1) & 1) * QKV_STG_W * 4;
#pragma unroll
            for (int i = 0; i < 4; i++)
                cp16(db + (ra[i] * 40 + qa4[i] * 4) * 4,
                     hnw + (p0 + ra[i]) * 128 + (ch + 1) * 32 + qa4[i] * 4);
#pragma unroll
            for (int i = 0; i < 8; i++)
                cp16(db + (QKV_A_W + rb[i] * 40 + qb4[i] * 4) * 4,
                     wbw + (o0 + rb[i]) * 128 + (ch + 1) * 32 + qb4[i] * 4);
            CP_COMMIT();
        }
        const uint32_t* Aw = sbuf + (ch & 1) * QKV_STG_W;
        const uint32_t* Bw = Aw + QKV_A_W;

        uint32_t a[4][4];
#pragma unroll
        for (int ks = 0; ks < 4; ks++) {
            uint2 t0 = *(const uint2*)(Aw + (w * 16 + g)     * 40 + ks * 8 + 2 * tig);
            uint2 t1 = *(const uint2*)(Aw + (w * 16 + g + 8) * 40 + ks * 8 + 2 * tig);
            a[ks][0] = t0.x; a[ks][1] = t1.x; a[ks][2] = t0.y; a[ks][3] = t1.y;
        }
#pragma unroll
        for (int nt = 0; nt < 16; nt++) {
            const uint32_t* bb = Bw + (nt * 8 + g) * 40 + 2 * tig;
#pragma unroll
            for (int ks = 0; ks < 4; ks++) {
                uint2 t = *(const uint2*)(bb + ks * 8);
                mma_bf16(acc[nt], a[ks][0], a[ks][1], a[ks][2], a[ks][3], t.x, t.y);
            }
        }
    }

    if (z < 2) {
        const float s = (z == 0) ? QSCALE2 : 1.f;
        uint32_t* dst = (uint32_t*)((z == 0) ? g_qb : g_kb);
        const int p = p0 + w * 16 + g;
#pragma unroll
        for (int nt = 0; nt < 16; nt++) {
            const int o = o0 + nt * 8 + 2 * tig;
            const float b0 = bias[o], b1 = bias[o + 1];
            const int wi = (o0 >> 4) * 8 + (nt >> 1) * 8 + 2 * tig + (nt & 1);
            dst[p * 128 + wi]       = pk_bf2((acc[nt][0] + b0) * s, (acc[nt][1] + b1) * s);
            dst[(p + 8) * 128 + wi] = pk_bf2((acc[nt][2] + b0) * s, (acc[nt][3] + b1) * s);
        }
    } else {
        __syncthreads();
        __nv_bfloat16* Vs = (__nv_bfloat16*)sbuf;   // [o 128][perm p 64] pitch 66
        const int plA = perm16(w * 16 + g), plB = perm16(w * 16 + g + 8);
#pragma unroll
        for (int nt = 0; nt < 16; nt++) {
            const int ol = nt * 8 + 2 * tig;
            const float b0 = bias[o0 + ol], b1 = bias[o0 + ol + 1];
            Vs[ol * 66 + plA]       = __float2bfloat16(acc[nt][0] + b0);
            Vs[(ol + 1) * 66 + plA] = __float2bfloat16(acc[nt][1] + b1);
            Vs[ol * 66 + plB]       = __float2bfloat16(acc[nt][2] + b0);
            Vs[(ol + 1) * 66 + plB] = __float2bfloat16(acc[nt][3] + b1);
        }
        __syncthreads();
        uint32_t* vtw = (uint32_t*)g_vtb;
        const uint32_t* vsw = (const uint32_t*)Vs;
#pragma unroll
        for (int i = 0; i < 32; i++) {
            int e = i * 128 + tid;
            int r = e >> 5, cc = e & 31;
            vtw[(o0 + r) * 2048 + (p0 >> 1) + cc] = vsw[r * 33 + cc];
        }
    }
}

// ---------------------------------------------------------------------------
// Kernel 3: attention, split-K x4, 128-key tiles processed in two 64-key
// halves, 2-stage cp.async ring, one barrier per 128 keys.
// K tile: 128 keys x 40 words (perm chans). V tile: 64 chans x 72 words
// (128 perm keys + pad). Smem 2 x 38912 B = 77824 B, 2 CTAs/SM.
// ---------------------------------------------------------------------------
#define KPITCH 40
#define VPITCH 72
#define K_W   (128 * KPITCH)
#define V_W   (64 * VPITCH)
#define STG_W (K_W + V_W)
#define KT2   ((N / NSPLIT) / 128)     // 8 big tiles per split
#define ATTN_SMEM (2 * STG_W * 4)

__global__ __launch_bounds__(256, 2) void attn_mma_kernel() {
    extern __shared__ uint32_t dbuf[];

    const int tid  = threadIdx.x;
    const int w    = tid >> 5, lane = tid & 31;
    const int g    = lane >> 2, tig = lane & 3;
    const int head = blockIdx.y;
    const int q0   = blockIdx.x * 128;
    const int spl  = blockIdx.z;
    const int k0   = spl * (N / NSPLIT);

    const __nv_bfloat16* gq  = g_qb  + head * HD;
    const __nv_bfloat16* gk  = g_kb  + head * HD + k0 * C;
    const __nv_bfloat16* gvt = g_vtb + head * HD * N + k0;

    uint32_t qa[4][4];
    {
        const int r0 = q0 + w * 16 + g;
#pragma unroll
        for (int ks = 0; ks < 4; ks++) {
            uint2 t0 = *(const uint2*)(gq +  r0      * C + ks * 16 + 4 * tig);
            uint2 t1 = *(const uint2*)(gq + (r0 + 8) * C + ks * 16 + 4 * tig);
            qa[ks][0] = t0.x; qa[ks][1] = t1.x; qa[ks][2] = t0.y; qa[ks][3] = t1.y;
        }
    }

    const uint32_t sb = smem_u32(dbuf);
    // K: 4 uint4/thread (128 rows x 8 uint4); V: 4 uint4/thread (64 rows x 16)
    int kr[4], kq[4], vr[4], vq[4];
#pragma unroll
    for (int i = 0; i < 4; i++) {
        int e = i * 256 + tid;
        kr[i] = e >> 3;  kq[i] = e & 7;
        vr[i] = e >> 4;  vq[i] = e & 15;
    }

    float oacc[8][4] = {};
    float l0 = 0.f, l1 = 0.f;

    // prologue: tile 0 -> stage 0
#pragma unroll
    for (int i = 0; i < 4; i++) {
        cp16(sb + (kr[i] * KPITCH + kq[i] * 4) * 4, gk + kr[i] * C + kq[i] * 8);
        cp16(sb + (K_W + vr[i] * VPITCH + vq[i] * 4) * 4, gvt + vr[i] * N + vq[i] * 8);
    }
    CP_COMMIT();

    for (int kt = 0; kt < KT2; kt++) {
        CP_WAIT0();
        __syncthreads();
        if (kt + 1 < KT2) {
            const uint32_t db = sb + ((kt + 1) & 1) * STG_W * 4;
            const __nv_bfloat16* ks_src = gk + (kt + 1) * 128 * C;
            const __nv_bfloat16* vs_src = gvt + (kt + 1) * 128;
#pragma unroll
            for (int i = 0; i < 4; i++) {
                cp16(db + (kr[i] * KPITCH + kq[i] * 4) * 4,
                     ks_src + kr[i] * C + kq[i] * 8);
                cp16(db + (K_W + vr[i] * VPITCH + vq[i] * 4) * 4,
                     vs_src + vr[i] * N + vq[i] * 8);
            }
            CP_COMMIT();
        }

        const uint32_t* Kc = dbuf + (kt & 1) * STG_W;
        const uint32_t* Vc = Kc + K_W;

#pragma unroll
        for (int h = 0; h < 2; h++) {
            float p[8][4];
#pragma unroll
            for (int nt = 0; nt < 8; nt++) {
                float s[4] = {};
                const uint32_t* kb = Kc + (h * 64 + nt * 8 + g) * KPITCH + 2 * tig;
#pragma unroll
                for (int ks = 0; ks < 4; ks++) {
                    uint2 b = *(const uint2*)(kb + ks * 8);
                    mma_bf16(s, qa[ks][0], qa[ks][1], qa[ks][2], qa[ks][3], b.x, b.y);
                }
                p[nt][0] = ex2(s[0]); p[nt][1] = ex2(s[1]);
                p[nt][2] = ex2(s[2]); p[nt][3] = ex2(s[3]);
                l0 += p[nt][0] + p[nt][1];
                l1 += p[nt][2] + p[nt][3];
            }

#pragma unroll
            for (int ks = 0; ks < 4; ks++) {
                const uint32_t pa0 = pk_bf2(p[2 * ks][0],     p[2 * ks][1]);
                const uint32_t pa1 = pk_bf2(p[2 * ks][2],     p[2 * ks][3]);
                const uint32_t pa2 = pk_bf2(p[2 * ks + 1][0], p[2 * ks + 1][1]);
                const uint32_t pa3 = pk_bf2(p[2 * ks + 1][2], p[2 * ks + 1][3]);
                const uint32_t* vb = Vc + g * VPITCH + h * 32 + ks * 8 + 2 * tig;
#pragma unroll
                for (int nt = 0; nt < 8; nt++) {
                    uint2 b = *(const uint2*)(vb + nt * 8 * VPITCH);
                    mma_bf16(oacc[nt], pa0, pa1, pa2, pa3, b.x, b.y);
                }
            }
        }
    }

    l0 += __shfl_xor_sync(0xffffffffu, l0, 1);
    l0 += __shfl_xor_sync(0xffffffffu, l0, 2);
    l1 += __shfl_xor_sync(0xffffffffu, l1, 1);
    l1 += __shfl_xor_sync(0xffffffffu, l1, 2);

    const int r0 = q0 + w * 16 + g;
    if (tig == 0) {
        g_pl[(spl * HEADS + head) * N + r0]     = l0;
        g_pl[(spl * HEADS + head) * N + r0 + 8] = l1;
    }
    float* po = g_po + spl * N * C;
#pragma unroll
    for (int nt = 0; nt < 8; nt++) {
        const int col = head * HD + nt * 8 + 2 * tig;
        *(float2*)(po + r0 * C + col)       = make_float2(oacc[nt][0], oacc[nt][1]);
        *(float2*)(po + (r0 + 8) * C + col) = make_float2(oacc[nt][2], oacc[nt][3]);
    }
}

// ---------------------------------------------------------------------------
// Kernel 3c: combine 4 partials (+inline 1/l), normalize, transpose to
// g_ot[p2][perm8 c] (tf32) (validated r15/r16).
// ---------------------------------------------------------------------------
__global__ void combine_t_kernel() {
    __shared__ float T[64 * 65];
    __shared__ float linv_s[64];
    const int tid = threadIdx.x;
    const int p0 = blockIdx.x * 64;
    const int c0 = blockIdx.y * 64;

    const int head = (p0 >> 6) & 3;
    const int pixoff = p0 >> 8;
    if (tid < 64) {
        int pidx = head * N + (c0 + tid) * 16 + pixoff;
        float l = 0.f;
#pragma unroll
        for (int s = 0; s < NSPLIT; s++) l += g_pl[s * HEADS * N + pidx];
        linv_s[tid] = 1.f / l;
    }
    __syncthreads();

#pragma unroll
    for (int i = 0; i < 16; i++) {
        int idx = tid + i * 256;
        int cl = idx >> 6, pl = idx & 63;
        int f = (c0 + cl) * N + p0 + pl;
        float v = 0.f;
#pragma unroll
        for (int s = 0; s < NSPLIT; s++) v += g_po[s * N * C + f];
        T[cl * 65 + pl] = v * linv_s[cl];
    }
    __syncthreads();
#pragma unroll
    for (int i = 0; i < 16; i++) {
        int idx = tid + i * 256;
        int pl = idx >> 6, cl = idx & 63;
        int cperm = c0 + (cl & ~7) + wpos8(cl & 7);
        g_ot[(p0 + pl) * 256 + cperm] = tf32r(T[cl * 65 + pl]);
    }
}

// ---------------------------------------------------------------------------
// Kernel 4: proj via tf32 mma + residual, cp.async pipelined (validated r16).
// ---------------------------------------------------------------------------
#define PRJ_A_W   (64 * 40)
#define PRJ_STG_W (PRJ_A_W + 128 * 40)
#define PRJ_SMEM  (2 * PRJ_STG_W * 4)

__global__ __launch_bounds__(128, 2) void proj_mma_kernel(
        const float* __restrict__ bp,
        const float* __restrict__ x, float* __restrict__ out) {
    extern __shared__ uint32_t pbuf[];

    const int tid = threadIdx.x;
    const int w = tid >> 5, lane = tid & 31;
    const int g = lane >> 2, tig = lane & 3;
    const int p0 = blockIdx.x * 128;
    const int o0 = blockIdx.y * 64;

    const uint32_t* wpt = (const uint32_t*)g_wpt;
    const uint32_t* otw = (const uint32_t*)g_ot;

    const uint32_t sb = smem_u32(pbuf);
    int ra[4], qa4[4], rb[8], qb4[8];
#pragma unroll
    for (int i = 0; i < 4; i++) {
        int e = i * 128 + tid;
        ra[i] = e >> 3; qa4[i] = e & 7;
    }
#pragma unroll
    for (int i = 0; i < 8; i++) {
        int e = i * 128 + tid;
        rb[i] = e >> 3; qb4[i] = e & 7;
    }

    float acc[16][4] = {};

#pragma unroll
    for (int i = 0; i < 4; i++)
        cp16(sb + (ra[i] * 40 + qa4[i] * 4) * 4,
             wpt + (o0 + ra[i]) * 256 + qa4[i] * 4);
#pragma unroll
    for (int i = 0; i < 8; i++)
        cp16(sb + (PRJ_A_W + rb[i] * 40 + qb4[i] * 4) * 4,
             otw + (p0 + rb[i]) * 256 + qb4[i] * 4);
    CP_COMMIT();

    for (int ch = 0; ch < 8; ch++) {
        CP_WAIT0();
        __syncthreads();
        if (ch < 7) {
            const uint32_t db = sb + ((ch + 1) & 1) * PRJ_STG_W * 4;
#pragma unroll
            for (int i = 0; i < 4; i++)
                cp16(db + (ra[i] * 40 + qa4[i] * 4) * 4,
                     wpt + (o0 + ra[i]) * 256 + (ch + 1) * 32 + qa4[i] * 4);
#pragma unroll
            for (int i = 0; i < 8; i++)
                cp16(db + (PRJ_A_W + rb[i] * 40 + qb4[i] * 4) * 4,
                     otw + (p0 + rb[i]) * 256 + (ch + 1) * 32 + qb4[i] * 4);
            CP_COMMIT();
        }
        const uint32_t* Aw = pbuf + (ch & 1) * PRJ_STG_W;
        const uint32_t* Bw = Aw + PRJ_A_W;

        uint32_t a[4][4];
#pragma unroll
        for (int ks = 0; ks < 4; ks++) {
            uint2 t0 = *(const uint2*)(Aw + (w * 16 + g)     * 40 + ks * 8 + 2 * tig);
            uint2 t1 = *(const uint2*)(Aw + (w * 16 + g + 8) * 40 + ks * 8 + 2 * tig);
            a[ks][0] = t0.x; a[ks][1] = t1.x; a[ks][2] = t0.y; a[ks][3] = t1.y;
        }
#pragma unroll
        for (int nt = 0; nt < 16; nt++) {
            const uint32_t* bb = Bw + (nt * 8 + g) * 40 + 2 * tig;
#pragma unroll
            for (int ks = 0; ks < 4; ks++) {
                uint2 t = *(const uint2*)(bb + ks * 8);
                mma_tf32(acc[nt], a[ks][0], a[ks][1], a[ks][2], a[ks][3], t.x, t.y);
            }
        }
    }

    const int oo = o0 + w * 16 + g;
    const float b0 = bp[oo], b1 = bp[oo + 8];
#pragma unroll
    for (int nt = 0; nt < 16; nt++) {
        const int pp = p0 + nt * 8 + 2 * tig;
        float2 x0 = *(const float2*)(x + oo * N + pp);
        float2 x1 = *(const float2*)(x + (oo + 8) * N + pp);
        *(float2*)(out + oo * N + pp) =
            make_float2(x0.x + b0 + acc[nt][0], x0.y + b0 + acc[nt][1]);
        *(float2*)(out + (oo + 8) * N + pp) =
            make_float2(x1.x + b1 + acc[nt][2], x1.y + b1 + acc[nt][3]);
    }
}

// ---------------------------------------------------------------------------
extern "C" void kernel_launch(void* const* d_in, const int* in_sizes, int n_in,
                              void* d_out, int out_size) {
    const float* x     = (const float*)d_in[0];
    const float* gamma = (const float*)d_in[1];
    const float* beta  = (const float*)d_in[2];
    const float* Wq    = (const float*)d_in[3];
    const float* bq    = (const float*)d_in[4];
    const float* Wk    = (const float*)d_in[5];
    const float* bk    = (const float*)d_in[6];
    const float* Wv    = (const float*)d_in[7];
    const float* bv    = (const float*)d_in[8];
    const float* Wp    = (const float*)d_in[9];
    const float* bp    = (const float*)d_in[10];
    float* out = (float*)d_out;

    cudaFuncSetAttribute(attn_mma_kernel,
                         cudaFuncAttributeMaxDynamicSharedMemorySize, ATTN_SMEM);
    cudaFuncSetAttribute(qkv_mma_kernel,
                         cudaFuncAttributeMaxDynamicSharedMemorySize, QKV_SMEM);
    cudaFuncSetAttribute(proj_mma_kernel,
                         cudaFuncAttributeMaxDynamicSharedMemorySize, PRJ_SMEM);

    prep_kernel<<<768, 256>>>(x, Wq, Wk, Wv, Wp);

    dim3 ga(8, 16);
    gn_apply_kernel<<<ga, 256>>>(x, gamma, beta);

    dim3 g2(N / 64, C / 128, 3);
    qkv_mma_kernel<<<g2, 128, QKV_SMEM>>>(bq, bk, bv);

    dim3 g3(N / 128, HEADS, NSPLIT);
    attn_mma_kernel<<<g3, 256, ATTN_SMEM>>>();

    dim3 gc(N / 64, C / 64);
    combine_t_kernel<<<gc, 256>>>();

    dim3 g4(N / 128, C / 64);
    proj_mma_kernel<<<g4, 128, PRJ_SMEM>>>(bp, x, out);
}